// round 11
// baseline (speedup 1.0000x reference)
#include <cuda_runtime.h>

#define BB 128
#define GG 20000
#define NELEM (BB * GG)        // 2,560,000
#define HID 64
#define KB 9                   // NUM_BINS - 1
#define NSEG (HID + 1)         // 65 piecewise-linear segments
#define ACROW 10               // padded row: 10 float2 = 80B
#define NTAB 4096
#define LOG2E 1.44269504088896340736f
#define TPB_A 512
#define GRID_A (NELEM / TPB_A) // 5000
#define TPB_B 256
#define GRID_B 1000

// Piecewise-linear tables: segment s -> logit_k*log2(e) = A*x + C
__device__ float         g_T[HID];
__device__ float2        g_AC[NSEG * ACROW];
__device__ unsigned char g_Tab[NTAB];

// Compaction state (self-restoring across graph replays)
__device__ float2 g_Work[NELEM];        // (idx as float bits, x)
__device__ int    g_Count  = 0;         // restored to 0 by kernel B's last block
__device__ int    g_Remain = GRID_B;    // restored to GRID_B likewise

__device__ __forceinline__ float ex2(float v) {
    float r;
    asm("ex2.approx.f32 %0, %1;" : "=f"(r) : "f"(v));
    return r;
}

__device__ __forceinline__ unsigned int mono_key(float x) {
    unsigned int u = __float_as_uint(x);
    return ((int)u < 0) ? ~u : (u | 0x80000000u);
}

// ---------------------------------------------------------------------------
// Kernel A: block 0 builds the tables; all blocks do coalesced zero-pattern
// prefill + mask + nonzero compaction into g_Work.
// ---------------------------------------------------------------------------
__device__ __forceinline__ float4 zpat(int r) {  // r = (float4 idx) % 5
    return make_float4(r == 0 ? 1.0f : 0.0f, 0.0f,
                       r == 2 ? 1.0f : 0.0f, 0.0f);
}

__global__ void __launch_bounds__(TPB_A) kernelA(const float* __restrict__ expr,
                                                 const float* __restrict__ W1,
                                                 const float* __restrict__ b1,
                                                 const float* __restrict__ W2,
                                                 const float* __restrict__ b2,
                                                 float* __restrict__ out) {
    __shared__ int sWarpCnt[TPB_A / 32];
    __shared__ int sWarpOff[TPB_A / 32];
    __shared__ int sBase;

    int tid = threadIdx.x;

    // ---- block 0: inline precompute (tables consumed only by kernel B) ----
    if (blockIdx.x == 0) {
        __shared__ float w1s[HID], b1s[HID], W2s[HID * KB], b2s[KB];
        __shared__ float t[HID], srt[HID];
        __shared__ unsigned int ku[HID];

        // strided preloads: sizes may exceed TPB_A (W2s is 576 > 512!)
        for (int i = tid; i < HID; i += TPB_A) { w1s[i] = W1[i]; b1s[i] = b1[i]; }
        for (int i = tid; i < HID * KB; i += TPB_A) W2s[i] = W2[i];
        for (int i = tid; i < KB; i += TPB_A) b2s[i] = b2[i];
        __syncthreads();

        if (tid < HID) {
            float w = w1s[tid], b = b1s[tid];
            float tv = (w != 0.0f) ? (-b / w) : 1e30f;
            if (!(tv > -1e30f)) tv = -1e30f;
            if (tv > 1e30f)     tv = 1e30f;
            t[tid] = tv;
        }
        __syncthreads();

        if (tid < HID) {     // rank sort
            float tv = t[tid];
            int rank = 0;
            #pragma unroll 8
            for (int i = 0; i < HID; i++) {
                float o = t[i];
                rank += (o < tv || (o == tv && i < tid)) ? 1 : 0;
            }
            srt[rank] = tv;
        }
        __syncthreads();

        if (tid < HID) { g_T[tid] = srt[tid]; ku[tid] = mono_key(srt[tid]); }

        for (int p = tid; p < NSEG * KB; p += TPB_A) {
            int s = p / KB;
            int k = p - s * KB;
            float xm;
            if (s == 0)        xm = srt[0] - 1.0f;
            else if (s == HID) xm = srt[HID - 1] + 1.0f;
            else               xm = 0.5f * srt[s - 1] + 0.5f * srt[s];

            float A = 0.0f, C = b2s[k];
            #pragma unroll 4
            for (int j = 0; j < HID; j++) {
                float w = w1s[j], b = b1s[j];
                float h = fmaf(xm, w, b);
                float c = (h >= 0.0f) ? 1.0f : 0.01f;
                float wv = W2s[j * KB + k];
                A = fmaf(c * w, wv, A);
                C = fmaf(c * b, wv, C);
            }
            g_AC[s * ACROW + k] = make_float2(A * LOG2E, C * LOG2E);
        }
        __syncthreads();

        for (int i = tid; i < NTAB; i += TPB_A) {
            unsigned int bkey = (unsigned int)i << 20;
            int pos = 0;
            #pragma unroll
            for (int step = 32; step >= 1; step >>= 1)
                if (ku[pos + step - 1] < bkey) pos += step;
            g_Tab[i] = (unsigned char)pos;
        }
    }

    // ---- common: prefill + mask + compaction ----
    size_t eBase = (size_t)blockIdx.x * TPB_A;
    float x = expr[eBase + tid];

    float4* dst = reinterpret_cast<float4*>(out + eBase * 10);
    {
        int i0 = tid;
        int i1 = tid + TPB_A;
        int i2 = tid + 2 * TPB_A;
        dst[i0] = zpat(i0 % 5);
        dst[i1] = zpat(i1 % 5);
        if (i2 < TPB_A * 10 / 4) dst[i2] = zpat(i2 % 5);
    }

    out[(size_t)NELEM * 10 + eBase + tid] = (x != 0.0f) ? 1.0f : 0.0f;

    // warp ballot + block scan + one global atomic per block
    int lane = tid & 31;
    int wid  = tid >> 5;
    unsigned bal = __ballot_sync(0xFFFFFFFFu, x != 0.0f);
    int rank = __popc(bal & ((1u << lane) - 1u));
    if (lane == 0) sWarpCnt[wid] = __popc(bal);
    __syncthreads();

    if (tid == 0) {
        int acc = 0;
        #pragma unroll
        for (int w = 0; w < TPB_A / 32; w++) {
            sWarpOff[w] = acc;
            acc += sWarpCnt[w];
        }
        sBase = atomicAdd(&g_Count, acc);
    }
    __syncthreads();

    if (x != 0.0f) {
        int gidx = (int)(eBase + tid);
        g_Work[sBase + sWarpOff[wid] + rank] =
            make_float2(__int_as_float(gidx), x);
    }
}

// ---------------------------------------------------------------------------
// Kernel B: full-warp processing of the compacted worklist.
// ---------------------------------------------------------------------------
__global__ void __launch_bounds__(TPB_B) kernelB(float* __restrict__ out) {
    int count = g_Count;

    for (int i = blockIdx.x * TPB_B + threadIdx.x; i < count;
         i += GRID_B * TPB_B) {
        float2 w = g_Work[i];
        int   idx = __float_as_int(w.x);
        float x   = w.y;

        int pos = __ldg(&g_Tab[mono_key(x) >> 20]);
        while (pos < HID && __ldg(&g_T[pos]) < x) pos++;

        const float4* row = reinterpret_cast<const float4*>(g_AC + pos * ACROW);
        float4 r0 = __ldg(row + 0);
        float4 r1 = __ldg(row + 1);
        float4 r2 = __ldg(row + 2);
        float4 r3 = __ldg(row + 3);
        float2 r4 = __ldg(reinterpret_cast<const float2*>(row + 4));

        float e0 = ex2(fmaf(r0.x, x, r0.y));
        float e1 = ex2(fmaf(r0.z, x, r0.w));
        float e2 = ex2(fmaf(r1.x, x, r1.y));
        float e3 = ex2(fmaf(r1.z, x, r1.w));
        float e4 = ex2(fmaf(r2.x, x, r2.y));
        float e5 = ex2(fmaf(r2.z, x, r2.w));
        float e6 = ex2(fmaf(r3.x, x, r3.y));
        float e7 = ex2(fmaf(r3.z, x, r3.w));
        float e8 = ex2(fmaf(r4.x, x, r4.y));

        float s = (((e0 + e1) + (e2 + e3)) + ((e4 + e5) + (e6 + e7))) + e8;
        float inv = __fdividef(1.0f, s);

        float2* q = reinterpret_cast<float2*>(out + (size_t)idx * 10);
        q[0] = make_float2(0.0f,     e0 * inv);
        q[1] = make_float2(e1 * inv, e2 * inv);
        q[2] = make_float2(e3 * inv, e4 * inv);
        q[3] = make_float2(e5 * inv, e6 * inv);
        q[4] = make_float2(e7 * inv, e8 * inv);
    }

    // self-restoring reset: the last block to exit restores replay invariants.
    __syncthreads();
    if (threadIdx.x == 0) {
        if (atomicSub(&g_Remain, 1) == 1) {
            g_Count  = 0;
            g_Remain = GRID_B;
            __threadfence();
        }
    }
}

// ---------------------------------------------------------------------------
extern "C" void kernel_launch(void* const* d_in, const int* in_sizes, int n_in,
                              void* d_out, int out_size) {
    const float* expr = (const float*)d_in[0];
    const float* W1   = (const float*)d_in[1];
    const float* b1   = (const float*)d_in[2];
    const float* W2   = (const float*)d_in[3];
    const float* b2   = (const float*)d_in[4];
    float* out = (float*)d_out;

    kernelA<<<GRID_A, TPB_A>>>(expr, W1, b1, W2, b2, out);
    kernelB<<<GRID_B, TPB_B>>>(out);
}

// round 15
// speedup vs baseline: 1.1098x; 1.1098x over previous
#include <cuda_runtime.h>

#define BB 128
#define GG 20000
#define NELEM (BB * GG)        // 2,560,000
#define HID 64
#define KB 9                   // NUM_BINS - 1
#define NSEG (HID + 1)         // 65 piecewise-linear segments
#define ACROW 10               // padded row: 10 float2 = 80B
#define NTAB 4096
#define LOG2E 1.44269504088896340736f
#define TPB 512
#define NW (TPB / 32)

// Piecewise-linear tables: segment s -> logit_k*log2(e) = A*x + C
__device__ float         g_T[HID];
__device__ float2        g_AC[NSEG * ACROW];
__device__ unsigned char g_Tab[NTAB];

__device__ __forceinline__ float ex2(float v) {
    float r;
    asm("ex2.approx.f32 %0, %1;" : "=f"(r) : "f"(v));
    return r;
}

__device__ __forceinline__ unsigned int mono_key(float x) {
    unsigned int u = __float_as_uint(x);
    return ((int)u < 0) ? ~u : (u | 0x80000000u);
}

// ---------------------------------------------------------------------------
// Precompute kernel: 1 block, 640 threads. Cheap (binary-search table build).
// ---------------------------------------------------------------------------
__global__ void precompute_kernel(const float* __restrict__ W1,
                                  const float* __restrict__ b1,
                                  const float* __restrict__ W2,
                                  const float* __restrict__ b2) {
    __shared__ float w1s[HID], b1s[HID], W2s[HID * KB], b2s[KB];
    __shared__ float t[HID], srt[HID];
    __shared__ unsigned int ku[HID];
    int tid = threadIdx.x;

    if (tid < HID)      { w1s[tid] = W1[tid]; b1s[tid] = b1[tid]; }
    if (tid < HID * KB) { W2s[tid] = W2[tid]; }      // 576 < 640 threads: OK
    if (tid < KB)       { b2s[tid] = b2[tid]; }
    __syncthreads();

    if (tid < HID) {
        float w = w1s[tid], b = b1s[tid];
        float tv = (w != 0.0f) ? (-b / w) : 1e30f;
        if (!(tv > -1e30f)) tv = -1e30f;
        if (tv > 1e30f)     tv = 1e30f;
        t[tid] = tv;
    }
    __syncthreads();

    if (tid < HID) {   // rank sort (64 elements)
        float tv = t[tid];
        int rank = 0;
        #pragma unroll 8
        for (int i = 0; i < HID; i++) {
            float o = t[i];
            rank += (o < tv || (o == tv && i < tid)) ? 1 : 0;
        }
        srt[rank] = tv;
    }
    __syncthreads();

    if (tid < HID) { g_T[tid] = srt[tid]; ku[tid] = mono_key(srt[tid]); }

    if (tid < NSEG * KB) {
        int s = tid / KB;
        int k = tid - s * KB;
        float xm;
        if (s == 0)        xm = srt[0] - 1.0f;
        else if (s == HID) xm = srt[HID - 1] + 1.0f;
        else               xm = 0.5f * srt[s - 1] + 0.5f * srt[s];

        float A = 0.0f, C = b2s[k];
        #pragma unroll 4
        for (int j = 0; j < HID; j++) {
            float w = w1s[j], b = b1s[j];
            float h = fmaf(xm, w, b);
            float c = (h >= 0.0f) ? 1.0f : 0.01f;
            float wv = W2s[j * KB + k];
            A = fmaf(c * w, wv, A);
            C = fmaf(c * b, wv, C);
        }
        g_AC[s * ACROW + k] = make_float2(A * LOG2E, C * LOG2E);
    }
    __syncthreads();

    // g_Tab[i] = #(keys < (i<<20)) via binary search on sorted keys
    for (int i = tid; i < NTAB; i += 640) {
        unsigned int bkey = (unsigned int)i << 20;
        int pos = 0;
        #pragma unroll
        for (int step = 32; step >= 1; step >>= 1)
            if (ku[pos + step - 1] < bkey) pos += step;
        g_Tab[i] = (unsigned char)pos;
    }
}

// ---------------------------------------------------------------------------
// Main kernel: per block — coalesced zero-pattern prefill + mask, block-local
// compaction of nonzeros into an smem worklist, then ~2 full warps process
// the expensive path for the whole block.
// ---------------------------------------------------------------------------
__device__ __forceinline__ float4 zpat(int r) {  // r = (float4 idx) % 5
    return make_float4(r == 0 ? 1.0f : 0.0f, 0.0f,
                       r == 2 ? 1.0f : 0.0f, 0.0f);
}

__global__ void __launch_bounds__(TPB) expr_quant_kernel(const float* __restrict__ expr,
                                                         float* __restrict__ out) {
    __shared__ float sX[TPB];       // worklist: x values
    __shared__ short sIdx[TPB];     // worklist: block-local element index
    __shared__ int   sWarpOff[NW];
    __shared__ int   sCnt;

    int tid = threadIdx.x;
    size_t eBase = (size_t)blockIdx.x * TPB;

    float x = expr[eBase + tid];               // coalesced 4B/lane

    // ---- phase 1: coalesced zero-pattern prefill (whole block slice) ----
    float4* dst = reinterpret_cast<float4*>(out + eBase * 10);
    {
        int i0 = tid;
        int i1 = tid + TPB;
        int i2 = tid + 2 * TPB;
        dst[i0] = zpat(i0 % 5);
        dst[i1] = zpat(i1 % 5);
        if (i2 < TPB * 10 / 4) dst[i2] = zpat(i2 % 5);
    }

    // mask (coalesced 4B/lane)
    out[(size_t)NELEM * 10 + eBase + tid] = (x != 0.0f) ? 1.0f : 0.0f;

    // ---- compaction into smem worklist ----
    int lane = tid & 31;
    int wid  = tid >> 5;
    unsigned bal = __ballot_sync(0xFFFFFFFFu, x != 0.0f);
    int wrank = __popc(bal & ((1u << lane) - 1u));
    if (lane == 0) sWarpOff[wid] = __popc(bal);
    __syncthreads();

    if (tid == 0) {
        int acc = 0;
        #pragma unroll
        for (int w = 0; w < NW; w++) {
            int c = sWarpOff[w];
            sWarpOff[w] = acc;
            acc += c;
        }
        sCnt = acc;
    }
    __syncthreads();

    if (x != 0.0f) {
        int slot = sWarpOff[wid] + wrank;
        sX[slot]   = x;
        sIdx[slot] = (short)tid;
    }
    __syncthreads();

    // ---- phase 2: full-warp expensive path over ~10% of elements ----
    int cnt = sCnt;
    if (tid < cnt) {
        float xv  = sX[tid];
        int   loc = sIdx[tid];

        int pos = __ldg(&g_Tab[mono_key(xv) >> 20]);
        while (pos < HID && __ldg(&g_T[pos]) < xv) pos++;

        const float4* row = reinterpret_cast<const float4*>(g_AC + pos * ACROW);
        float4 r0 = __ldg(row + 0);
        float4 r1 = __ldg(row + 1);
        float4 r2 = __ldg(row + 2);
        float4 r3 = __ldg(row + 3);
        float2 r4 = __ldg(reinterpret_cast<const float2*>(row + 4));

        float e0 = ex2(fmaf(r0.x, xv, r0.y));
        float e1 = ex2(fmaf(r0.z, xv, r0.w));
        float e2 = ex2(fmaf(r1.x, xv, r1.y));
        float e3 = ex2(fmaf(r1.z, xv, r1.w));
        float e4 = ex2(fmaf(r2.x, xv, r2.y));
        float e5 = ex2(fmaf(r2.z, xv, r2.w));
        float e6 = ex2(fmaf(r3.x, xv, r3.y));
        float e7 = ex2(fmaf(r3.z, xv, r3.w));
        float e8 = ex2(fmaf(r4.x, xv, r4.y));

        float s = (((e0 + e1) + (e2 + e3)) + ((e4 + e5) + (e6 + e7))) + e8;
        float inv = __fdividef(1.0f, s);

        // 40B row, 8B-aligned -> 5x STG.64 (overwrites prefill; __syncthreads
        // above gives CTA-scope ordering)
        float2* q = reinterpret_cast<float2*>(out + (eBase + (size_t)loc) * 10);
        q[0] = make_float2(0.0f,     e0 * inv);
        q[1] = make_float2(e1 * inv, e2 * inv);
        q[2] = make_float2(e3 * inv, e4 * inv);
        q[3] = make_float2(e5 * inv, e6 * inv);
        q[4] = make_float2(e7 * inv, e8 * inv);
    }
}

// ---------------------------------------------------------------------------
extern "C" void kernel_launch(void* const* d_in, const int* in_sizes, int n_in,
                              void* d_out, int out_size) {
    const float* expr = (const float*)d_in[0];
    const float* W1   = (const float*)d_in[1];
    const float* b1   = (const float*)d_in[2];
    const float* W2   = (const float*)d_in[3];
    const float* b2   = (const float*)d_in[4];
    float* out = (float*)d_out;

    precompute_kernel<<<1, 640>>>(W1, b1, W2, b2);
    expr_quant_kernel<<<NELEM / TPB, TPB>>>(expr, out);
}